// round 5
// baseline (speedup 1.0000x reference)
#include <cuda_runtime.h>
#include <cstdint>
#include <math.h>

// ---------------- problem constants ----------------
#define TOK   4096
#define RNUM  8
#define DDIM  768
#define FDIM  3072
#define VDIM  2048

// ---------------- device scratch ----------------
__device__ __align__(256) float g_Aperm[(size_t)TOK * DDIM];   // gathered + tf32-rounded activations
__device__ __align__(256) float g_H[(size_t)TOK * FDIM];       // relu(x@W1+b1), permuted, tf32-rounded
__device__ __align__(256) float g_logits[(size_t)TOK * VDIM];  // h@W2+b2, permuted rows
__device__ __align__(256) float g_W1t[(size_t)RNUM * FDIM * DDIM];  // W1^T [r][n][k], tf32-rounded
__device__ __align__(256) float g_W2t[(size_t)RNUM * VDIM * FDIM];  // W2^T [r][n][k], tf32-rounded
__device__ int g_perm[TOK];
__device__ int g_seg_start[RNUM + 1];

// ---------------- helpers ----------------
__device__ __forceinline__ uint32_t smem_u32(const void* p) {
    return (uint32_t)__cvta_generic_to_shared(p);
}
__device__ __forceinline__ void cp16(uint32_t s, const void* g) {
    asm volatile("cp.async.cg.shared.global [%0], [%1], 16;\n" :: "r"(s), "l"(g));
}
__device__ __forceinline__ uint32_t f2tf32(float x) {
    uint32_t o;
    asm("cvt.rna.tf32.f32 %0, %1;\n" : "=r"(o) : "f"(x));
    return o;
}
__device__ __forceinline__ float round_tf32(float x) {
    return __uint_as_float(f2tf32(x));
}
__device__ __forceinline__ void ldsm4(uint32_t* r, uint32_t addr) {
    asm volatile("ldmatrix.sync.aligned.m8n8.x4.shared.b16 {%0,%1,%2,%3}, [%4];\n"
                 : "=r"(r[0]), "=r"(r[1]), "=r"(r[2]), "=r"(r[3]) : "r"(addr));
}
__device__ __forceinline__ void mma_tf32(float* c, const uint32_t* a, const uint32_t* b) {
    asm volatile(
        "mma.sync.aligned.m16n8k8.row.col.f32.tf32.tf32.f32 "
        "{%0,%1,%2,%3},{%4,%5,%6,%7},{%8,%9},{%0,%1,%2,%3};\n"
        : "+f"(c[0]), "+f"(c[1]), "+f"(c[2]), "+f"(c[3])
        : "r"(a[0]), "r"(a[1]), "r"(a[2]), "r"(a[3]), "r"(b[0]), "r"(b[1]));
}

// ---------------- kernel 1: bucket tokens by route ----------------
__global__ void bucket_kernel(const int* __restrict__ route_ids) {
    __shared__ int s_cnt[RNUM];
    __shared__ int s_cur[RNUM];
    const int t = threadIdx.x;
    if (t < RNUM) s_cnt[t] = 0;
    __syncthreads();
    for (int i = t; i < TOK; i += blockDim.x)
        atomicAdd(&s_cnt[route_ids[i]], 1);
    __syncthreads();
    if (t == 0) {
        int off = 0;
        for (int r = 0; r < RNUM; r++) {
            g_seg_start[r] = off;
            s_cur[r] = off;
            off += s_cnt[r];
        }
        g_seg_start[RNUM] = off;
    }
    __syncthreads();
    for (int i = t; i < TOK; i += blockDim.x) {
        int r = route_ids[i];
        int pos = atomicAdd(&s_cur[r], 1);
        g_perm[pos] = i;
    }
}

// ---------------- kernel 2: gather A rows by perm, round to tf32 ----------------
__global__ __launch_bounds__(192)
void gather_kernel(const float* __restrict__ e_two) {
    const int row = blockIdx.x;
    const int tok = g_perm[row];
    const float4* src = reinterpret_cast<const float4*>(e_two + (size_t)tok * DDIM);
    float4* dst = reinterpret_cast<float4*>(g_Aperm + (size_t)row * DDIM);
    float4 v = src[threadIdx.x];
    v.x = round_tf32(v.x); v.y = round_tf32(v.y);
    v.z = round_tf32(v.z); v.w = round_tf32(v.w);
    dst[threadIdx.x] = v;
}

// ---------------- kernel 3: transpose + tf32-round weights ----------------
// W[r][K][N] -> Wt[r][N][K], value = round_tf32(w). 32x32 tiles, coalesced both ways.
__global__ __launch_bounds__(256)
void transpose_round_kernel(const float* __restrict__ W, float* __restrict__ Wt,
                            int K, int N) {
    __shared__ float t[32][33];
    const int r  = blockIdx.z;
    const float* Wr  = W  + (size_t)r * K * N;
    float*       Wtr = Wt + (size_t)r * N * K;
    const int k0 = blockIdx.x * 32;
    const int n0 = blockIdx.y * 32;
    const int tx = threadIdx.x;          // 0..31
    const int ty = threadIdx.y;          // 0..7
    #pragma unroll
    for (int i = 0; i < 4; i++)
        t[ty + 8 * i][tx] = Wr[(size_t)(k0 + ty + 8 * i) * N + n0 + tx];
    __syncthreads();
    #pragma unroll
    for (int i = 0; i < 4; i++)
        Wtr[(size_t)(n0 + ty + 8 * i) * K + k0 + tx] = round_tf32(t[tx][ty + 8 * i]);
}

// ---------------- tf32 GEMM: ldmatrix for BOTH operands ----------------
// C[128x128] = A[128 x K] @ Bt[n][k]^T (+bias, optional relu+round)
// BK=32, 3-stage cp.async pipeline; per iter: wait -> sync -> prefetch -> compute.
// 8 warps: 2(m) x 4(n), warp tile 64x32, mma m16n8k8 tf32, zero cvt in loop.
static constexpr int BK = 32;
static constexpr int TSTRIDE = 36;                       // 32 + 4 pad floats
static constexpr int TILE_FLOATS = 128 * TSTRIDE;        // one operand tile (A or B)
static constexpr int STAGE_FLOATS = 2 * TILE_FLOATS;     // A + B
static constexpr int NSTAGE = 3;
static constexpr int SMEM_BYTES = NSTAGE * STAGE_FLOATS * 4;   // 110,592 B

template <int KTOT, int NTOT, bool RELU>
__global__ void __launch_bounds__(256, 2)
gemm_tt(const float* __restrict__ Abase,
        const float* __restrict__ Btbase,
        const float* __restrict__ biasBase,
        float* __restrict__ Cbase) {
    constexpr int NK = KTOT / BK;

    extern __shared__ float smem[];   // [NSTAGE][ A:128x36 | B:128x36 ]

    const int r    = blockIdx.z;
    const int seg0 = g_seg_start[r];
    const int cnt  = g_seg_start[r + 1] - seg0;
    const int m0   = blockIdx.y * 128;
    if (m0 >= cnt) return;
    const int n0 = blockIdx.x * 128;

    const float* Bt   = Btbase + (size_t)r * (size_t)KTOT * NTOT;
    const float* bias = biasBase + (size_t)r * NTOT;

    const int tid  = threadIdx.x;
    const int warp = tid >> 5;
    const int lane = tid & 31;
    const int wm = warp & 1;    // 2 warp-rows of 64
    const int wn = warp >> 1;   // 4 warp-cols of 32
    const int lg = lane >> 2;
    const int lt = lane & 3;

    // loader: each stage = A 128x32 + B 128x32 floats (1024+1024 16B chunks; 8/thread)
    const int ld_row = tid >> 3;          // 0..31 (x4 blocks of 32)
    const int ld_ch  = tid & 7;           // 16B chunk within 32-float row
    auto load_tile = [&](int kt, int buf) {
        const int k0 = kt * BK;
        float* dA = smem + buf * STAGE_FLOATS;
        float* dB = dA + TILE_FLOATS;
        #pragma unroll
        for (int i = 0; i < 4; i++) {
            int row = ld_row + i * 32;
            int grow = seg0 + m0 + row;
            if (grow > TOK - 1) grow = TOK - 1;     // clamp; stores guarded
            cp16(smem_u32(dA + row * TSTRIDE + ld_ch * 4),
                 Abase + (size_t)grow * KTOT + k0 + ld_ch * 4);
        }
        #pragma unroll
        for (int i = 0; i < 4; i++) {
            int row = ld_row + i * 32;               // Bt row = output column n0+row
            cp16(smem_u32(dB + row * TSTRIDE + ld_ch * 4),
                 Bt + (size_t)(n0 + row) * KTOT + k0 + ld_ch * 4);
        }
        asm volatile("cp.async.commit_group;\n");
    };

    float acc[4][4][4];
    #pragma unroll
    for (int mt = 0; mt < 4; mt++)
        #pragma unroll
        for (int nt = 0; nt < 4; nt++)
            #pragma unroll
            for (int j = 0; j < 4; j++) acc[mt][nt][j] = 0.f;

    // ldmatrix lane addresses (bytes, within a stage buffer)
    const int a_row = wm * 64 + (lane & 7) + (((lane >> 3) & 1) << 3);
    const int a_colb = (((lane >> 4) & 1) << 4);
    const uint32_t aBase = smem_u32(smem) + (uint32_t)(a_row * TSTRIDE * 4 + a_colb);
    const int b_row = wn * 32 + (lane & 7) + (((lane >> 4) & 1) << 3);
    const int b_colb = (((lane >> 3) & 1) << 4);
    const uint32_t bBase = smem_u32(smem) + (uint32_t)(TILE_FLOATS * 4 + b_row * TSTRIDE * 4 + b_colb);

    load_tile(0, 0);
    load_tile(1, 1);

    for (int kt = 0; kt < NK; kt++) {
        const int buf = kt % NSTAGE;
        // group kt complete for THIS thread...
        asm volatile("cp.async.wait_group 1;\n");
        // ...and for ALL threads; also: everyone done reading buffer (kt+2)%3 (iter kt-1)
        __syncthreads();
        // prefetch stage kt+2 (empty commit at tail keeps group accounting exact)
        if (kt + 2 < NK) load_tile(kt + 2, (kt + 2) % NSTAGE);
        else asm volatile("cp.async.commit_group;\n");

        const uint32_t aBuf = aBase + buf * (STAGE_FLOATS * 4);
        const uint32_t bBuf = bBase + buf * (STAGE_FLOATS * 4);

        #pragma unroll
        for (int ks = 0; ks < 4; ks++) {
            uint32_t afr[4][4];
            #pragma unroll
            for (int mt = 0; mt < 4; mt++)
                ldsm4(afr[mt], aBuf + mt * (16 * TSTRIDE * 4) + ks * 32);

            uint32_t bfr[4][2];
            #pragma unroll
            for (int ntp = 0; ntp < 2; ntp++) {
                uint32_t q[4];
                ldsm4(q, bBuf + ntp * (16 * TSTRIDE * 4) + ks * 32);
                bfr[2 * ntp + 0][0] = q[0];
                bfr[2 * ntp + 0][1] = q[1];
                bfr[2 * ntp + 1][0] = q[2];
                bfr[2 * ntp + 1][1] = q[3];
            }
            #pragma unroll
            for (int mt = 0; mt < 4; mt++)
                #pragma unroll
                for (int nt = 0; nt < 4; nt++)
                    mma_tf32(acc[mt][nt], afr[mt], bfr[nt]);
        }
    }

    __syncthreads();

    // epilogue: bias (+relu+tf32-round for phase1), guarded float2 stores
    #pragma unroll
    for (int mt = 0; mt < 4; mt++) {
        #pragma unroll
        for (int half = 0; half < 2; half++) {
            const int rowl = wm * 64 + mt * 16 + lg + half * 8;
            const int mrow = m0 + rowl;
            if (mrow < cnt) {
                float* crow = Cbase + (size_t)(seg0 + mrow) * NTOT;
                #pragma unroll
                for (int nt = 0; nt < 4; nt++) {
                    const int col = n0 + wn * 32 + nt * 8 + lt * 2;
                    float v0 = acc[mt][nt][half * 2 + 0] + bias[col];
                    float v1 = acc[mt][nt][half * 2 + 1] + bias[col + 1];
                    if (RELU) {
                        v0 = round_tf32(fmaxf(v0, 0.f));
                        v1 = round_tf32(fmaxf(v1, 0.f));
                    }
                    *reinterpret_cast<float2*>(crow + col) = make_float2(v0, v1);
                }
            }
        }
    }
}

// ---------------- softmax + scatter to real token rows ----------------
__global__ __launch_bounds__(256)
void softmax_kernel(float* __restrict__ out) {
    const int i   = blockIdx.x;
    const int tok = g_perm[i];
    const float* lrow = g_logits + (size_t)i * VDIM;
    float*       orow = out + (size_t)tok * VDIM;
    const int tid = threadIdx.x;

    float v[8];
    float mx = -1e30f;
    #pragma unroll
    for (int j = 0; j < 8; j++) {
        v[j] = lrow[tid + 256 * j];
        mx = fmaxf(mx, v[j]);
    }
    #pragma unroll
    for (int o = 16; o; o >>= 1) mx = fmaxf(mx, __shfl_xor_sync(0xffffffffu, mx, o));

    __shared__ float sred[8];
    const int w = tid >> 5;
    if ((tid & 31) == 0) sred[w] = mx;
    __syncthreads();
    float bmx = sred[0];
    #pragma unroll
    for (int j = 1; j < 8; j++) bmx = fmaxf(bmx, sred[j]);

    float s = 0.f;
    #pragma unroll
    for (int j = 0; j < 8; j++) {
        v[j] = expf(v[j] - bmx);
        s += v[j];
    }
    #pragma unroll
    for (int o = 16; o; o >>= 1) s += __shfl_xor_sync(0xffffffffu, s, o);
    __syncthreads();
    if ((tid & 31) == 0) sred[w] = s;
    __syncthreads();
    float tot = 0.f;
    #pragma unroll
    for (int j = 0; j < 8; j++) tot += sred[j];
    const float inv = 1.f / tot;
    #pragma unroll
    for (int j = 0; j < 8; j++) orow[tid + 256 * j] = v[j] * inv;
}

// ---------------- launch ----------------
extern "C" void kernel_launch(void* const* d_in, const int* in_sizes, int n_in,
                              void* d_out, int out_size) {
    const float* e_two     = (const float*)d_in[0];   // [4,1024,768]
    const int*   route_ids = (const int*)d_in[1];     // [4,1024]
    const float* W1        = (const float*)d_in[2];   // [8,768,3072]
    const float* b1        = (const float*)d_in[3];   // [8,3072]
    const float* W2        = (const float*)d_in[4];   // [8,3072,2048]
    const float* b2        = (const float*)d_in[5];   // [8,2048]
    float*       out       = (float*)d_out;           // [4,1024,2048]

    void *pA, *pH, *pL, *pW1t, *pW2t;
    cudaGetSymbolAddress(&pA,   g_Aperm);
    cudaGetSymbolAddress(&pH,   g_H);
    cudaGetSymbolAddress(&pL,   g_logits);
    cudaGetSymbolAddress(&pW1t, g_W1t);
    cudaGetSymbolAddress(&pW2t, g_W2t);

    static bool attr_done = false;
    if (!attr_done) {
        cudaFuncSetAttribute(gemm_tt<DDIM, FDIM, true>,
                             cudaFuncAttributeMaxDynamicSharedMemorySize, SMEM_BYTES);
        cudaFuncSetAttribute(gemm_tt<FDIM, VDIM, false>,
                             cudaFuncAttributeMaxDynamicSharedMemorySize, SMEM_BYTES);
        attr_done = true;
    }

    bucket_kernel<<<1, 512>>>(route_ids);
    gather_kernel<<<TOK, 192>>>(e_two);

    // weight transpose + tf32 rounding (every call; no caching allowed)
    {
        dim3 blk(32, 8);
        dim3 gt1(DDIM / 32, FDIM / 32, RNUM);   // (24, 96, 8)
        transpose_round_kernel<<<gt1, blk>>>(W1, (float*)pW1t, DDIM, FDIM);
        dim3 gt2(FDIM / 32, VDIM / 32, RNUM);   // (96, 64, 8)
        transpose_round_kernel<<<gt2, blk>>>(W2, (float*)pW2t, FDIM, VDIM);
    }

    dim3 g1(FDIM / 128, TOK / 128, RNUM);   // (24, 32, 8)
    gemm_tt<DDIM, FDIM, true><<<g1, 256, SMEM_BYTES>>>(
        (const float*)pA, (const float*)pW1t, b1, (float*)pH);

    dim3 g2(VDIM / 128, TOK / 128, RNUM);   // (16, 32, 8)
    gemm_tt<FDIM, VDIM, false><<<g2, 256, SMEM_BYTES>>>(
        (const float*)pH, (const float*)pW2t, b2, (float*)pL);

    softmax_kernel<<<TOK, 256>>>(out);
}